// round 7
// baseline (speedup 1.0000x reference)
#include <cuda_runtime.h>

#define B_ 2
#define V_ 20000
#define C_ 32
#define NB_ 12
#define KS_ 9
#define OUT_ 32
#define NNODES (B_*V_)
#define KDIM (KS_*C_)     /* 288 */
#define KP (KDIM/2)       /* 144 c-pairs */
#define MT_ 64            /* nodes per block; 625 blocks exact */
#define RS_ 64            /* row slots in transposed y (XOR-swizzled) */

typedef unsigned long long u64;

// Scratch (module-allocated)
__device__ float g_ep[NNODES * 12];   // exp(ux+c), padded to 12 (pads=0)
__device__ float g_em[NNODES * 12];   // exp(-ux),  padded to 12 (pads=0)
__device__ u64   g_wp[KP * OUT_];     // W pre-paired over c: 36 KB, L1/L2-hot

#define FMA_F32X2(d, a, b) \
    asm("fma.rn.f32x2 %0, %1, %2, %0;" : "+l"(d) : "l"(a), "l"(b))

__device__ __forceinline__ u64 pack2(float a, float b) {
    u64 r; asm("mov.b64 %0, {%1,%2};" : "=l"(r) : "f"(a), "f"(b)); return r;
}
__device__ __forceinline__ float lo32(u64 v) {
    float a, b; asm("mov.b64 {%0,%1}, %2;" : "=f"(a), "=f"(b) : "l"(v)); return a;
}
__device__ __forceinline__ float hi32(u64 v) {
    float a, b; asm("mov.b64 {%0,%1}, %2;" : "=f"(a), "=f"(b) : "l"(v)); return b;
}
__device__ __forceinline__ float hsum(u64 v) { return lo32(v) + hi32(v); }

// ---------------------------------------------------------------------------
// Kernel 1: ux = x.u ; store E+[k]=exp(ux+c), E-[k]=exp(-ux), 12-padded.
// Block 0 additionally stages g_wp (paired W layout).
// ---------------------------------------------------------------------------
__global__ void __launch_bounds__(512) k_ux(const float* __restrict__ x,
                                            const float* __restrict__ u,
                                            const float* __restrict__ cvec,
                                            const float* __restrict__ W) {
    __shared__ float u_sm[C_ * KS_];
    __shared__ float c_sm[KS_];
    for (int i = threadIdx.x; i < C_ * KS_; i += 512) u_sm[i] = u[i];
    if (threadIdx.x < KS_) c_sm[threadIdx.x] = cvec[threadIdx.x];
    __syncthreads();

    if (blockIdx.x == 0) {
        // stage paired W: g_wp[kp*32+o] = (W[2j][k][o], W[2j+1][k][o]), kp=k*16+j
        for (int idx = threadIdx.x; idx < KP * OUT_; idx += 512) {
            int kp = idx >> 5, o = idx & 31;
            int k = kp >> 4, j = kp & 15;
            g_wp[idx] = pack2(W[(2 * j) * KDIM + k * OUT_ + o],
                              W[(2 * j + 1) * KDIM + k * OUT_ + o]);
        }
    }

    int t = blockIdx.x * 512 + threadIdx.x;
    int node = t >> 2;
    int qq = t & 3;
    bool valid = node < NNODES;
    int nc = valid ? node : (NNODES - 1);

    const float4* xr = reinterpret_cast<const float4*>(x + (size_t)nc * C_) + qq * 2;
    float4 v0 = xr[0];
    float4 v1 = xr[1];
    float xs[8] = {v0.x, v0.y, v0.z, v0.w, v1.x, v1.y, v1.z, v1.w};

    float acc[KS_];
#pragma unroll
    for (int k = 0; k < KS_; k++) acc[k] = 0.f;
    const int cbase = qq * 8;
#pragma unroll
    for (int j = 0; j < 8; j++)
#pragma unroll
        for (int k = 0; k < KS_; k++)
            acc[k] = fmaf(xs[j], u_sm[(cbase + j) * KS_ + k], acc[k]);
#pragma unroll
    for (int k = 0; k < KS_; k++) acc[k] += __shfl_xor_sync(0xffffffffu, acc[k], 1);
#pragma unroll
    for (int k = 0; k < KS_; k++) acc[k] += __shfl_xor_sync(0xffffffffu, acc[k], 2);

    if (valid && qq < 3) {
        float4 pe, me;
        if (qq < 2) {
            int kb = qq * 4;
            pe = make_float4(__expf(acc[kb] + c_sm[kb]),
                             __expf(acc[kb + 1] + c_sm[kb + 1]),
                             __expf(acc[kb + 2] + c_sm[kb + 2]),
                             __expf(acc[kb + 3] + c_sm[kb + 3]));
            me = make_float4(__expf(-acc[kb]), __expf(-acc[kb + 1]),
                             __expf(-acc[kb + 2]), __expf(-acc[kb + 3]));
        } else {
            pe = make_float4(__expf(acc[8] + c_sm[8]), 0.f, 0.f, 0.f);
            me = make_float4(__expf(-acc[8]), 0.f, 0.f, 0.f);
        }
        reinterpret_cast<float4*>(g_ep + (size_t)node * 12)[qq] = pe;
        reinterpret_cast<float4*>(g_em + (size_t)node * 12)[qq] = me;
    }
}

// ---------------------------------------------------------------------------
// Kernel 2 (fused): attention + aggregation into smem (transposed, swizzled),
// then GEMM out = relu(Y @ W2 + b). W read via broadcast LDG from g_wp.
// 512 threads, 2 blocks/SM (only yt + q in smem).
// ---------------------------------------------------------------------------
__global__ void __launch_bounds__(512, 2)
k_fused(const float* __restrict__ x, const float* __restrict__ bias,
        const int* __restrict__ adj, float* __restrict__ out) {
    extern __shared__ __align__(16) u64 yt[];   // [kp][row^] : KP*RS_ u64 = 72 KB
    __shared__ float q_sm[16][NB_ * 12];        // 9.2 KB

    const int tid = threadIdx.x;
    const int warp = tid >> 5;
    const int lane = tid & 31;
    const int row0 = blockIdx.x * MT_;

    // ---- Phase A: 16 warps x 4 nodes ----
    const int jj = lane >> 1;     // c-pair within k-group
    const int ee = lane & 1;      // element within pair
    float* y32 = reinterpret_cast<float*>(yt);

    // prefetch adj rows for all 4 nodes (hide gather latency across iterations)
    int av[4];
#pragma unroll
    for (int it = 0; it < 4; it++) {
        int node = row0 + warp * 4 + it;
        int v = node % V_;
        av[it] = (lane < NB_) ? adj[v * NB_ + lane] : 0;
    }

#pragma unroll
    for (int it = 0; it < 4; it++) {
        const int l = warp * 4 + it;
        const int node = row0 + l;
        const int b = node / V_;
        const int a = av[it];

        unsigned nz = __ballot_sync(0xffffffffu, a != 0);
        int deg = __popc(nz);
        float inv_deg = deg ? (1.f / (float)deg) : 0.f;

        if (lane < NB_) {
            float4* qr = reinterpret_cast<float4*>(&q_sm[warp][lane * 12]);
            if (a) {
                const float4* em4 = reinterpret_cast<const float4*>(
                    g_em + (size_t)(b * V_ + (a - 1)) * 12);
                const float4* ep4 = reinterpret_cast<const float4*>(
                    g_ep + (size_t)node * 12);
                float4 m0 = em4[0], m1 = em4[1], m2 = em4[2];
                float4 p0 = ep4[0], p1 = ep4[1], p2 = ep4[2];
                float q0 = p0.x * m0.x, q1 = p0.y * m0.y, q2 = p0.z * m0.z,
                      q3 = p0.w * m0.w;
                float q4 = p1.x * m1.x, q5 = p1.y * m1.y, q6 = p1.z * m1.z,
                      q7 = p1.w * m1.w;
                float q8 = p2.x * m2.x;
                float s = q0 + q1 + q2 + q3 + q4 + q5 + q6 + q7 + q8;
                float sc = inv_deg / s;
                qr[0] = make_float4(q0 * sc, q1 * sc, q2 * sc, q3 * sc);
                qr[1] = make_float4(q4 * sc, q5 * sc, q6 * sc, q7 * sc);
                qr[2] = make_float4(q8 * sc, 0.f, 0.f, 0.f);
            } else {
                qr[0] = make_float4(0.f, 0.f, 0.f, 0.f);
                qr[1] = make_float4(0.f, 0.f, 0.f, 0.f);
                qr[2] = make_float4(0.f, 0.f, 0.f, 0.f);
            }
        }
        __syncwarp();

        // batched neighbor gathers (MLP=12); q rows zero for missing neighbors
        float xv[NB_];
#pragma unroll
        for (int n = 0; n < NB_; n++) {
            int an = __shfl_sync(0xffffffffu, a, n);
            int idx = an ? (an - 1) : 0;
            xv[n] = x[((size_t)b * V_ + idx) * C_ + lane];
        }

        u64 acc[5];
#pragma unroll
        for (int t = 0; t < 5; t++) acc[t] = 0ull;
#pragma unroll
        for (int n = 0; n < NB_; n++) {
            u64 xx = pack2(xv[n], xv[n]);
            const u64* q64 = reinterpret_cast<const u64*>(&q_sm[warp][n * 12]);
#pragma unroll
            for (int t = 0; t < 5; t++) FMA_F32X2(acc[t], q64[t], xx);
        }

        // transposed, swizzled store (conflict-free): kp = k*16+jj, slot l^jj
        float vals[KS_] = {lo32(acc[0]), hi32(acc[0]), lo32(acc[1]), hi32(acc[1]),
                           lo32(acc[2]), hi32(acc[2]), lo32(acc[3]), hi32(acc[3]),
                           lo32(acc[4])};
        const int lsw = (l ^ jj);
#pragma unroll
        for (int k = 0; k < KS_; k++) {
            int kp = k * 16 + jj;
            y32[(kp * RS_ + lsw) * 2 + ee] = vals[k];
        }
        __syncwarp();
    }
    __syncthreads();

    // ---- Phase B: GEMM from smem y + broadcast-LDG W. thread=(row, 4-out grp) ----
    const int row = tid & 63;
    const int og = tid >> 6;            // 0..7, warp-uniform -> broadcast LDG

    u64 acc[4];
#pragma unroll
    for (int j = 0; j < 4; j++) acc[j] = 0ull;

    const ulonglong2* wp = reinterpret_cast<const ulonglong2*>(g_wp + og * 4);

#pragma unroll 16
    for (int kp = 0; kp < KP; kp++) {
        u64 yk = yt[kp * RS_ + (row ^ (kp & 15))];
        ulonglong2 w0 = __ldg(wp + kp * (OUT_ / 2));        // outs og*4, og*4+1
        ulonglong2 w1 = __ldg(wp + kp * (OUT_ / 2) + 1);    // outs og*4+2, og*4+3
        FMA_F32X2(acc[0], yk, w0.x);
        FMA_F32X2(acc[1], yk, w0.y);
        FMA_F32X2(acc[2], yk, w1.x);
        FMA_F32X2(acc[3], yk, w1.y);
    }

    const int ob = og * 4;
    float4 ov;
    ov.x = fmaxf(hsum(acc[0]) + __ldg(bias + ob + 0), 0.f);
    ov.y = fmaxf(hsum(acc[1]) + __ldg(bias + ob + 1), 0.f);
    ov.z = fmaxf(hsum(acc[2]) + __ldg(bias + ob + 2), 0.f);
    ov.w = fmaxf(hsum(acc[3]) + __ldg(bias + ob + 3), 0.f);
    *reinterpret_cast<float4*>(out + (size_t)(row0 + row) * OUT_ + ob) = ov;
}

// ---------------------------------------------------------------------------
// Inputs (metadata order): x, W, u, c, b, adj
// ---------------------------------------------------------------------------
extern "C" void kernel_launch(void* const* d_in, const int* in_sizes, int n_in,
                              void* d_out, int out_size) {
    const float* x    = (const float*)d_in[0];
    const float* W    = (const float*)d_in[1];
    const float* u    = (const float*)d_in[2];
    const float* cvec = (const float*)d_in[3];
    const float* bias = (const float*)d_in[4];
    const int*   adj  = (const int*)d_in[5];
    float* out = (float*)d_out;

    const int dsm_bytes = KP * RS_ * (int)sizeof(u64);  // 73728
    cudaFuncSetAttribute(k_fused, cudaFuncAttributeMaxDynamicSharedMemorySize,
                         dsm_bytes);

    k_ux<<<(NNODES * 4 + 511) / 512, 512>>>(x, u, cvec, W);
    k_fused<<<NNODES / MT_, 512, dsm_bytes>>>(x, bias, adj, out);
}

// round 8
// speedup vs baseline: 1.1875x; 1.1875x over previous
#include <cuda_runtime.h>

#define B_ 2
#define V_ 20000
#define C_ 32
#define NB_ 12
#define KS_ 9
#define OUT_ 32
#define NNODES (B_*V_)
#define KDIM 288          /* KS_*C_ */
#define MR2 40448         /* rows padded: 316 gemm blocks * 128 */

typedef unsigned long long u64;

// Scratch (module-allocated, zero-initialized; pad rows of g_yt never written)
__device__ float g_ep[NNODES * 12];            // exp(ux+c), padded to 12 (pads=0)
__device__ float g_em[NNODES * 12];            // exp(-ux),  padded to 12 (pads=0)
__device__ float g_yt[(size_t)KDIM * MR2];     // TRANSPOSED y: [i][row], 46.6 MB

#define FMA_F32X2(d, a, b) \
    asm("fma.rn.f32x2 %0, %1, %2, %0;" : "+l"(d) : "l"(a), "l"(b))

__device__ __forceinline__ u64 pack2(float a, float b) {
    u64 r; asm("mov.b64 %0, {%1,%2};" : "=l"(r) : "f"(a), "f"(b)); return r;
}
__device__ __forceinline__ float lo32(u64 v) {
    float a, b; asm("mov.b64 {%0,%1}, %2;" : "=f"(a), "=f"(b) : "l"(v)); return a;
}
__device__ __forceinline__ float hi32(u64 v) {
    float a, b; asm("mov.b64 {%0,%1}, %2;" : "=f"(a), "=f"(b) : "l"(v)); return b;
}

// ---------------------------------------------------------------------------
// Kernel 1: ux = x.u ; store E+[k]=exp(ux+c), E-[k]=exp(-ux), 12-padded.
// ---------------------------------------------------------------------------
__global__ void __launch_bounds__(512) k_ux(const float* __restrict__ x,
                                            const float* __restrict__ u,
                                            const float* __restrict__ cvec) {
    __shared__ float u_sm[C_ * KS_];
    __shared__ float c_sm[KS_];
    for (int i = threadIdx.x; i < C_ * KS_; i += 512) u_sm[i] = u[i];
    if (threadIdx.x < KS_) c_sm[threadIdx.x] = cvec[threadIdx.x];
    __syncthreads();

    int t = blockIdx.x * 512 + threadIdx.x;
    int node = t >> 2;
    int qq = t & 3;
    bool valid = node < NNODES;
    int nc = valid ? node : (NNODES - 1);

    const float4* xr = reinterpret_cast<const float4*>(x + (size_t)nc * C_) + qq * 2;
    float4 v0 = xr[0];
    float4 v1 = xr[1];
    float xs[8] = {v0.x, v0.y, v0.z, v0.w, v1.x, v1.y, v1.z, v1.w};

    float acc[KS_];
#pragma unroll
    for (int k = 0; k < KS_; k++) acc[k] = 0.f;
    const int cbase = qq * 8;
#pragma unroll
    for (int j = 0; j < 8; j++)
#pragma unroll
        for (int k = 0; k < KS_; k++)
            acc[k] = fmaf(xs[j], u_sm[(cbase + j) * KS_ + k], acc[k]);
#pragma unroll
    for (int k = 0; k < KS_; k++) acc[k] += __shfl_xor_sync(0xffffffffu, acc[k], 1);
#pragma unroll
    for (int k = 0; k < KS_; k++) acc[k] += __shfl_xor_sync(0xffffffffu, acc[k], 2);

    if (valid && qq < 3) {
        float4 pe, me;
        if (qq < 2) {
            int kb = qq * 4;
            pe = make_float4(__expf(acc[kb] + c_sm[kb]),
                             __expf(acc[kb + 1] + c_sm[kb + 1]),
                             __expf(acc[kb + 2] + c_sm[kb + 2]),
                             __expf(acc[kb + 3] + c_sm[kb + 3]));
            me = make_float4(__expf(-acc[kb]), __expf(-acc[kb + 1]),
                             __expf(-acc[kb + 2]), __expf(-acc[kb + 3]));
        } else {
            pe = make_float4(__expf(acc[8] + c_sm[8]), 0.f, 0.f, 0.f);
            me = make_float4(__expf(-acc[8]), 0.f, 0.f, 0.f);
        }
        reinterpret_cast<float4*>(g_ep + (size_t)node * 12)[qq] = pe;
        reinterpret_cast<float4*>(g_em + (size_t)node * 12)[qq] = me;
    }
}

// ---------------------------------------------------------------------------
// Kernel 2: attention + aggregation, output TRANSPOSED to g_yt[i][node].
// 32 nodes/block (8 warps x 4). Smem staging tile, XOR-swizzled (conflict-free),
// then fully coalesced STG to g_yt.
// ---------------------------------------------------------------------------
__global__ void __launch_bounds__(256) k_attn(const float* __restrict__ x,
                                              const int* __restrict__ adj) {
    __shared__ float yb[KDIM * 32];       // 36 KB: [i][slot], slot = l ^ (i&31)
    __shared__ float q_sm[8][NB_ * 12];

    const int tid = threadIdx.x;
    const int warp = tid >> 5;
    const int lane = tid & 31;
    const int node0 = blockIdx.x * 32;    // grid = 1250 exact

    // prefetch adj rows for this warp's 4 nodes
    int av[4];
#pragma unroll
    for (int it = 0; it < 4; it++) {
        int node = node0 + warp * 4 + it;
        int v = node % V_;
        av[it] = (lane < NB_) ? adj[v * NB_ + lane] : 0;
    }

#pragma unroll
    for (int it = 0; it < 4; it++) {
        const int l = warp * 4 + it;
        const int node = node0 + l;
        const int b = node / V_;
        const int a = av[it];

        unsigned nz = __ballot_sync(0xffffffffu, a != 0);
        int deg = __popc(nz);
        float inv_deg = deg ? (1.f / (float)deg) : 0.f;

        if (lane < NB_) {
            float4* qr = reinterpret_cast<float4*>(&q_sm[warp][lane * 12]);
            if (a) {
                const float4* em4 = reinterpret_cast<const float4*>(
                    g_em + (size_t)(b * V_ + (a - 1)) * 12);
                const float4* ep4 = reinterpret_cast<const float4*>(
                    g_ep + (size_t)node * 12);
                float4 m0 = em4[0], m1 = em4[1], m2 = em4[2];
                float4 p0 = ep4[0], p1 = ep4[1], p2 = ep4[2];
                float q0 = p0.x * m0.x, q1 = p0.y * m0.y, q2 = p0.z * m0.z,
                      q3 = p0.w * m0.w;
                float q4 = p1.x * m1.x, q5 = p1.y * m1.y, q6 = p1.z * m1.z,
                      q7 = p1.w * m1.w;
                float q8 = p2.x * m2.x;
                float s = q0 + q1 + q2 + q3 + q4 + q5 + q6 + q7 + q8;
                float sc = inv_deg / s;
                qr[0] = make_float4(q0 * sc, q1 * sc, q2 * sc, q3 * sc);
                qr[1] = make_float4(q4 * sc, q5 * sc, q6 * sc, q7 * sc);
                qr[2] = make_float4(q8 * sc, 0.f, 0.f, 0.f);
            } else {
                qr[0] = make_float4(0.f, 0.f, 0.f, 0.f);
                qr[1] = make_float4(0.f, 0.f, 0.f, 0.f);
                qr[2] = make_float4(0.f, 0.f, 0.f, 0.f);
            }
        }
        __syncwarp();

        // batched neighbor gathers (MLP=12); q rows zero for missing neighbors
        float xv[NB_];
#pragma unroll
        for (int n = 0; n < NB_; n++) {
            int an = __shfl_sync(0xffffffffu, a, n);
            int idx = an ? (an - 1) : 0;
            xv[n] = x[((size_t)b * V_ + idx) * C_ + lane];
        }

        u64 acc[5];
#pragma unroll
        for (int t = 0; t < 5; t++) acc[t] = 0ull;
#pragma unroll
        for (int n = 0; n < NB_; n++) {
            u64 xx = pack2(xv[n], xv[n]);
            const u64* q64 = reinterpret_cast<const u64*>(&q_sm[warp][n * 12]);
#pragma unroll
            for (int t = 0; t < 5; t++) FMA_F32X2(acc[t], q64[t], xx);
        }

        // swizzled smem store: yb[(k*32+lane)*32 + (l ^ lane)] (conflict-free)
        float vals[KS_] = {lo32(acc[0]), hi32(acc[0]), lo32(acc[1]), hi32(acc[1]),
                           lo32(acc[2]), hi32(acc[2]), lo32(acc[3]), hi32(acc[3]),
                           lo32(acc[4])};
#pragma unroll
        for (int k = 0; k < KS_; k++)
            yb[(k * 32 + lane) * 32 + (l ^ lane)] = vals[k];
    }
    __syncthreads();

    // coalesced transposed write-out: g_yt[i][node0 + l]
#pragma unroll
    for (int idx = tid; idx < KDIM * 32; idx += 256) {
        int i = idx >> 5, l = idx & 31;
        g_yt[(size_t)i * MR2 + node0 + l] = yb[(i << 5) + (l ^ (i & 31))];
    }
}

// ---------------------------------------------------------------------------
// Kernel 3: out = relu(Yt^T @ W2 + b). Thread = one row; y loads coalesced
// LDG.32 from g_yt; W paired over OUTPUTS in smem -> acc[16] u64, no hsum.
// ---------------------------------------------------------------------------
__global__ void __launch_bounds__(128) k_gemm(const float* __restrict__ W,
                                              const float* __restrict__ bias,
                                              float* __restrict__ out) {
    __shared__ __align__(16) u64 ws[KDIM * 16];   // [i][opair], 36 KB
    __shared__ float b_sm[OUT_];

    const int tid = threadIdx.x;

    // ws[i*16+op] = (W2[i][2op], W2[i][2op+1]);  W2[k*32+c][o] = W[c][k][o]
    for (int idx = tid; idx < KDIM * 16; idx += 128) {
        int i = idx >> 4, op = idx & 15;
        int c = i & 31, k = i >> 5;
        const float* w = W + c * KDIM + k * OUT_ + 2 * op;
        ws[idx] = pack2(w[0], w[1]);
    }
    if (tid < OUT_) b_sm[tid] = bias[tid];
    __syncthreads();

    const int r = blockIdx.x * 128 + tid;   // < MR2; pad rows are zeros

    u64 acc[16];
#pragma unroll
    for (int op = 0; op < 16; op++) acc[op] = 0ull;

    const float* yp = g_yt + r;
#pragma unroll 4
    for (int i = 0; i < KDIM; i++) {
        float yv = __ldg(yp + (size_t)i * MR2);    // coalesced: 1 line/warp
        u64 yy = pack2(yv, yv);
        const ulonglong2* wr = reinterpret_cast<const ulonglong2*>(&ws[i * 16]);
#pragma unroll
        for (int o4 = 0; o4 < 8; o4++) {
            ulonglong2 w = wr[o4];                  // broadcast LDS.128
            FMA_F32X2(acc[2 * o4],     yy, w.x);
            FMA_F32X2(acc[2 * o4 + 1], yy, w.y);
        }
    }

    if (r < NNODES) {
        float* dst = out + (size_t)r * OUT_;
#pragma unroll
        for (int j = 0; j < 8; j++) {               // float4 per 2 acc pairs
            float4 ov;
            ov.x = fmaxf(lo32(acc[2 * j])     + b_sm[4 * j + 0], 0.f);
            ov.y = fmaxf(hi32(acc[2 * j])     + b_sm[4 * j + 1], 0.f);
            ov.z = fmaxf(lo32(acc[2 * j + 1]) + b_sm[4 * j + 2], 0.f);
            ov.w = fmaxf(hi32(acc[2 * j + 1]) + b_sm[4 * j + 3], 0.f);
            reinterpret_cast<float4*>(dst)[j] = ov;
        }
    }
}

// ---------------------------------------------------------------------------
// Inputs (metadata order): x, W, u, c, b, adj
// ---------------------------------------------------------------------------
extern "C" void kernel_launch(void* const* d_in, const int* in_sizes, int n_in,
                              void* d_out, int out_size) {
    const float* x    = (const float*)d_in[0];
    const float* W    = (const float*)d_in[1];
    const float* u    = (const float*)d_in[2];
    const float* cvec = (const float*)d_in[3];
    const float* bias = (const float*)d_in[4];
    const int*   adj  = (const int*)d_in[5];
    float* out = (float*)d_out;

    k_ux<<<(NNODES * 4 + 511) / 512, 512>>>(x, u, cvec);
    k_attn<<<NNODES / 32, 256>>>(x, adj);
    k_gemm<<<MR2 / 128, 128>>>(W, bias, out);
}

// round 9
// speedup vs baseline: 1.2504x; 1.0530x over previous
#include <cuda_runtime.h>

#define B_ 2
#define V_ 20000
#define C_ 32
#define NB_ 12
#define KS_ 9
#define OUT_ 32
#define NNODES (B_*V_)
#define KDIM 288          /* KS_*C_ */
#define MR2 40448         /* rows padded: 158 gemm blocks * 256 */

typedef unsigned long long u64;

// Scratch (module-allocated, zero-initialized; pad rows never written)
__device__ float g_ep[NNODES * 12];            // exp(ux+c), 12-padded (pads=0)
__device__ float g_em[NNODES * 16];            // exp(-ux), 16-padded 64B rows
__device__ float g_yt[(size_t)KDIM * MR2];     // TRANSPOSED y: [i][row], 46.6 MB

#define FMA_F32X2(d, a, b) \
    asm("fma.rn.f32x2 %0, %1, %2, %0;" : "+l"(d) : "l"(a), "l"(b))

__device__ __forceinline__ u64 pack2(float a, float b) {
    u64 r; asm("mov.b64 %0, {%1,%2};" : "=l"(r) : "f"(a), "f"(b)); return r;
}
__device__ __forceinline__ float lo32(u64 v) {
    float a, b; asm("mov.b64 {%0,%1}, %2;" : "=f"(a), "=f"(b) : "l"(v)); return a;
}
__device__ __forceinline__ float hi32(u64 v) {
    float a, b; asm("mov.b64 {%0,%1}, %2;" : "=f"(a), "=f"(b) : "l"(v)); return b;
}

// ---------------------------------------------------------------------------
// Kernel 1: ux = x.u ; E+[k]=exp(ux+c) (12-pad), E-[k]=exp(-ux) (16-pad rows).
// ---------------------------------------------------------------------------
__global__ void __launch_bounds__(512) k_ux(const float* __restrict__ x,
                                            const float* __restrict__ u,
                                            const float* __restrict__ cvec) {
    __shared__ float u_sm[C_ * KS_];
    __shared__ float c_sm[KS_];
    for (int i = threadIdx.x; i < C_ * KS_; i += 512) u_sm[i] = u[i];
    if (threadIdx.x < KS_) c_sm[threadIdx.x] = cvec[threadIdx.x];
    __syncthreads();

    int t = blockIdx.x * 512 + threadIdx.x;
    int node = t >> 2;
    int qq = t & 3;
    bool valid = node < NNODES;
    int nc = valid ? node : (NNODES - 1);

    const float4* xr = reinterpret_cast<const float4*>(x + (size_t)nc * C_) + qq * 2;
    float4 v0 = xr[0];
    float4 v1 = xr[1];
    float xs[8] = {v0.x, v0.y, v0.z, v0.w, v1.x, v1.y, v1.z, v1.w};

    float acc[KS_];
#pragma unroll
    for (int k = 0; k < KS_; k++) acc[k] = 0.f;
    const int cbase = qq * 8;
#pragma unroll
    for (int j = 0; j < 8; j++)
#pragma unroll
        for (int k = 0; k < KS_; k++)
            acc[k] = fmaf(xs[j], u_sm[(cbase + j) * KS_ + k], acc[k]);
#pragma unroll
    for (int k = 0; k < KS_; k++) acc[k] += __shfl_xor_sync(0xffffffffu, acc[k], 1);
#pragma unroll
    for (int k = 0; k < KS_; k++) acc[k] += __shfl_xor_sync(0xffffffffu, acc[k], 2);

    if (valid) {
        // em: 16-float row, thread qq writes float4 at 4*qq
        float4 me;
        if (qq == 0)
            me = make_float4(__expf(-acc[0]), __expf(-acc[1]), __expf(-acc[2]),
                             __expf(-acc[3]));
        else if (qq == 1)
            me = make_float4(__expf(-acc[4]), __expf(-acc[5]), __expf(-acc[6]),
                             __expf(-acc[7]));
        else if (qq == 2)
            me = make_float4(__expf(-acc[8]), 0.f, 0.f, 0.f);
        else
            me = make_float4(0.f, 0.f, 0.f, 0.f);
        reinterpret_cast<float4*>(g_em + (size_t)node * 16)[qq] = me;

        // ep: 12-float row, threads 0..2 write
        if (qq < 3) {
            float4 pe;
            if (qq < 2) {
                int kb = qq * 4;
                pe = make_float4(__expf(acc[kb] + c_sm[kb]),
                                 __expf(acc[kb + 1] + c_sm[kb + 1]),
                                 __expf(acc[kb + 2] + c_sm[kb + 2]),
                                 __expf(acc[kb + 3] + c_sm[kb + 3]));
            } else {
                pe = make_float4(__expf(acc[8] + c_sm[8]), 0.f, 0.f, 0.f);
            }
            reinterpret_cast<float4*>(g_ep + (size_t)node * 12)[qq] = pe;
        }
    }
}

// ---------------------------------------------------------------------------
// Kernel 2: attention + aggregation, output TRANSPOSED to g_yt[i][node].
// Cooperative em gather (4 lanes per neighbor row), q read via LDS.128.
// ---------------------------------------------------------------------------
#define EMS 20   /* smem stride (floats) for gathered em rows */
__global__ void __launch_bounds__(256) k_attn(const float* __restrict__ x,
                                              const int* __restrict__ adj) {
    __shared__ float yb[KDIM * 32];            // 36 KB staging
    __shared__ float q_sm[8][NB_ * 12];        // 4.6 KB
    __shared__ float em_sm[8][NB_ * EMS];      // 7.5 KB

    const int tid = threadIdx.x;
    const int warp = tid >> 5;
    const int lane = tid & 31;
    const int node0 = blockIdx.x * 32;         // grid = 1250 exact

    int av[4];
#pragma unroll
    for (int it = 0; it < 4; it++) {
        int node = node0 + warp * 4 + it;
        int v = node % V_;
        av[it] = (lane < NB_) ? adj[v * NB_ + lane] : 0;
    }

    const int n1 = lane >> 2, j1 = lane & 3;   // cooperative gather mapping

#pragma unroll
    for (int it = 0; it < 4; it++) {
        const int l = warp * 4 + it;
        const int node = node0 + l;
        const int b = node / V_;
        const int a = av[it];

        unsigned nz = __ballot_sync(0xffffffffu, a != 0);
        int deg = __popc(nz);
        float inv_deg = deg ? (1.f / (float)deg) : 0.f;

        // cooperative em gather: neighbors 0..7 (all lanes), 8..11 (lanes 0..15)
        int an1 = __shfl_sync(0xffffffffu, a, n1);
        int an2 = __shfl_sync(0xffffffffu, a, (8 + n1) & 31);
        {
            int s1 = an1 ? (an1 - 1) : 0;
            float4 v1 = *reinterpret_cast<const float4*>(
                g_em + (size_t)(b * V_ + s1) * 16 + 4 * j1);
            *reinterpret_cast<float4*>(&em_sm[warp][n1 * EMS + 4 * j1]) = v1;
            if (lane < 16) {
                int s2 = an2 ? (an2 - 1) : 0;
                float4 v2 = *reinterpret_cast<const float4*>(
                    g_em + (size_t)(b * V_ + s2) * 16 + 4 * j1);
                *reinterpret_cast<float4*>(&em_sm[warp][(8 + n1) * EMS + 4 * j1]) = v2;
            }
        }
        __syncwarp();

        if (lane < NB_) {
            float4* qr = reinterpret_cast<float4*>(&q_sm[warp][lane * 12]);
            if (a) {
                const float4* em4 = reinterpret_cast<const float4*>(
                    &em_sm[warp][lane * EMS]);
                const float4* ep4 = reinterpret_cast<const float4*>(
                    g_ep + (size_t)node * 12);
                float4 m0 = em4[0], m1 = em4[1], m2 = em4[2];
                float4 p0 = ep4[0], p1 = ep4[1], p2 = ep4[2];
                float q0 = p0.x * m0.x, q1 = p0.y * m0.y, q2 = p0.z * m0.z,
                      q3 = p0.w * m0.w;
                float q4 = p1.x * m1.x, q5 = p1.y * m1.y, q6 = p1.z * m1.z,
                      q7 = p1.w * m1.w;
                float q8 = p2.x * m2.x;
                float s = q0 + q1 + q2 + q3 + q4 + q5 + q6 + q7 + q8;
                float sc = inv_deg / s;
                qr[0] = make_float4(q0 * sc, q1 * sc, q2 * sc, q3 * sc);
                qr[1] = make_float4(q4 * sc, q5 * sc, q6 * sc, q7 * sc);
                qr[2] = make_float4(q8 * sc, 0.f, 0.f, 0.f);
            } else {
                qr[0] = make_float4(0.f, 0.f, 0.f, 0.f);
                qr[1] = make_float4(0.f, 0.f, 0.f, 0.f);
                qr[2] = make_float4(0.f, 0.f, 0.f, 0.f);
            }
        }
        __syncwarp();

        // batched neighbor x gathers (coalesced 128B rows, MLP=12)
        float xv[NB_];
#pragma unroll
        for (int n = 0; n < NB_; n++) {
            int an = __shfl_sync(0xffffffffu, a, n);
            int idx = an ? (an - 1) : 0;
            xv[n] = x[((size_t)b * V_ + idx) * C_ + lane];
        }

        u64 acc[5];
#pragma unroll
        for (int t = 0; t < 5; t++) acc[t] = 0ull;
#pragma unroll
        for (int n = 0; n < NB_; n++) {
            u64 xx = pack2(xv[n], xv[n]);
            const float4* q4 = reinterpret_cast<const float4*>(&q_sm[warp][n * 12]);
            float4 qa = q4[0], qb = q4[1], qc = q4[2];   // 3 broadcast LDS.128
            FMA_F32X2(acc[0], pack2(qa.x, qa.y), xx);
            FMA_F32X2(acc[1], pack2(qa.z, qa.w), xx);
            FMA_F32X2(acc[2], pack2(qb.x, qb.y), xx);
            FMA_F32X2(acc[3], pack2(qb.z, qb.w), xx);
            FMA_F32X2(acc[4], pack2(qc.x, qc.x), xx);    // hi lane unused
        }

        // swizzled smem store: yb[(k*32+lane)*32 + (l ^ lane)] (conflict-free)
        float vals[KS_] = {lo32(acc[0]), hi32(acc[0]), lo32(acc[1]), hi32(acc[1]),
                           lo32(acc[2]), hi32(acc[2]), lo32(acc[3]), hi32(acc[3]),
                           lo32(acc[4])};
#pragma unroll
        for (int k = 0; k < KS_; k++)
            yb[(k * 32 + lane) * 32 + (l ^ lane)] = vals[k];
    }
    __syncthreads();

    // coalesced transposed write-out: g_yt[i][node0 + l]
#pragma unroll
    for (int idx = tid; idx < KDIM * 32; idx += 256) {
        int i = idx >> 5, l = idx & 31;
        g_yt[(size_t)i * MR2 + node0 + l] = yb[(i << 5) + (l ^ (i & 31))];
    }
}

// ---------------------------------------------------------------------------
// Kernel 3: out = relu(Yt^T @ W2 + b). 256 thr, 256-row tile, 4 rows x 8 outs
// per thread. y double-buffered via coalesced chunks; W paired over outputs.
// ---------------------------------------------------------------------------
#define GMT 256
#define GCH 16
#define NCHK (KDIM / GCH)   /* 18 */
__global__ void __launch_bounds__(256) k_gemm(const float* __restrict__ W,
                                              const float* __restrict__ bias,
                                              float* __restrict__ out) {
    extern __shared__ __align__(16) char dsm_raw[];
    u64* ws = reinterpret_cast<u64*>(dsm_raw);                   // [i][opair], 36 KB
    float* ych = reinterpret_cast<float*>(dsm_raw + KDIM * 16 * 8); // 2x16x256, 32 KB
    __shared__ float b_sm[OUT_];

    const int tid = threadIdx.x;

    // ws[i*16+op] = (W2[i][2op], W2[i][2op+1]);  W2[k*32+c][o] = W[c][k][o]
    for (int idx = tid; idx < KDIM * 16; idx += 256) {
        int i = idx >> 4, op = idx & 15;
        int c = i & 31, k = i >> 5;
        const float* w = W + c * KDIM + k * OUT_ + 2 * op;
        ws[idx] = pack2(w[0], w[1]);
    }
    if (tid < OUT_) b_sm[tid] = bias[tid];

    const int row0 = blockIdx.x * GMT;
    const int warp = tid >> 5, lane = tid & 31;
    const int og = warp & 3;          // outs 8*og..8*og+7 (warp-uniform)
    const int rh = warp >> 2;         // row half
    const int rbase = rh * 128 + lane * 4;

    u64 acc[4][4];
#pragma unroll
    for (int r = 0; r < 4; r++)
#pragma unroll
        for (int p = 0; p < 4; p++) acc[r][p] = 0ull;

    // load chunk 0
#pragma unroll
    for (int e = 0; e < GCH; e++)
        ych[e * 256 + tid] = g_yt[(size_t)e * MR2 + row0 + tid];
    __syncthreads();

#pragma unroll 1
    for (int ch = 0; ch < NCHK; ch++) {
        const int buf = ch & 1;

        // issue next chunk's loads into registers (no STS dependency yet)
        float pre[GCH];
        if (ch + 1 < NCHK) {
#pragma unroll
            for (int e = 0; e < GCH; e++)
                pre[e] = g_yt[(size_t)((ch + 1) * GCH + e) * MR2 + row0 + tid];
        }

        const float* yc = &ych[buf * (GCH * 256)];
#pragma unroll
        for (int il = 0; il < GCH; il++) {
            const int i = ch * GCH + il;
            float4 yv = *reinterpret_cast<const float4*>(&yc[il * 256 + rbase]);
            u64 yy0 = pack2(yv.x, yv.x);
            u64 yy1 = pack2(yv.y, yv.y);
            u64 yy2 = pack2(yv.z, yv.z);
            u64 yy3 = pack2(yv.w, yv.w);
            const ulonglong2* wr =
                reinterpret_cast<const ulonglong2*>(&ws[i * 16 + og * 4]);
            ulonglong2 wa = wr[0];   // opairs og*4, og*4+1
            ulonglong2 wb = wr[1];   // opairs og*4+2, og*4+3
            FMA_F32X2(acc[0][0], yy0, wa.x); FMA_F32X2(acc[0][1], yy0, wa.y);
            FMA_F32X2(acc[0][2], yy0, wb.x); FMA_F32X2(acc[0][3], yy0, wb.y);
            FMA_F32X2(acc[1][0], yy1, wa.x); FMA_F32X2(acc[1][1], yy1, wa.y);
            FMA_F32X2(acc[1][2], yy1, wb.x); FMA_F32X2(acc[1][3], yy1, wb.y);
            FMA_F32X2(acc[2][0], yy2, wa.x); FMA_F32X2(acc[2][1], yy2, wa.y);
            FMA_F32X2(acc[2][2], yy2, wb.x); FMA_F32X2(acc[2][3], yy2, wb.y);
            FMA_F32X2(acc[3][0], yy3, wa.x); FMA_F32X2(acc[3][1], yy3, wa.y);
            FMA_F32X2(acc[3][2], yy3, wb.x); FMA_F32X2(acc[3][3], yy3, wb.y);
        }

        if (ch + 1 < NCHK) {
#pragma unroll
            for (int e = 0; e < GCH; e++)
                ych[(buf ^ 1) * (GCH * 256) + e * 256 + tid] = pre[e];
        }
        __syncthreads();
    }

    // epilogue: rows row0 + rbase + rr, outs 8*og..+7
    const int ob = og * 8;
#pragma unroll
    for (int rr = 0; rr < 4; rr++) {
        int grow = row0 + rbase + rr;
        if (grow < NNODES) {
            float4 oa, obv;
            oa.x  = fmaxf(lo32(acc[rr][0]) + b_sm[ob + 0], 0.f);
            oa.y  = fmaxf(hi32(acc[rr][0]) + b_sm[ob + 1], 0.f);
            oa.z  = fmaxf(lo32(acc[rr][1]) + b_sm[ob + 2], 0.f);
            oa.w  = fmaxf(hi32(acc[rr][1]) + b_sm[ob + 3], 0.f);
            obv.x = fmaxf(lo32(acc[rr][2]) + b_sm[ob + 4], 0.f);
            obv.y = fmaxf(hi32(acc[rr][2]) + b_sm[ob + 5], 0.f);
            obv.z = fmaxf(lo32(acc[rr][3]) + b_sm[ob + 6], 0.f);
            obv.w = fmaxf(hi32(acc[rr][3]) + b_sm[ob + 7], 0.f);
            float* dst = out + (size_t)grow * OUT_ + ob;
            reinterpret_cast<float4*>(dst)[0] = oa;
            reinterpret_cast<float4*>(dst)[1] = obv;
        }
    }
}

// ---------------------------------------------------------------------------
// Inputs (metadata order): x, W, u, c, b, adj
// ---------------------------------------------------------------------------
extern "C" void kernel_launch(void* const* d_in, const int* in_sizes, int n_in,
                              void* d_out, int out_size) {
    const float* x    = (const float*)d_in[0];
    const float* W    = (const float*)d_in[1];
    const float* u    = (const float*)d_in[2];
    const float* cvec = (const float*)d_in[3];
    const float* bias = (const float*)d_in[4];
    const int*   adj  = (const int*)d_in[5];
    float* out = (float*)d_out;

    const int dsm = KDIM * 16 * 8 + 2 * GCH * 256 * 4;   // 36864 + 32768 = 69632
    cudaFuncSetAttribute(k_gemm, cudaFuncAttributeMaxDynamicSharedMemorySize, dsm);

    k_ux<<<(NNODES * 4 + 511) / 512, 512>>>(x, u, cvec);
    k_attn<<<NNODES / 32, 256>>>(x, adj);
    k_gemm<<<MR2 / GMT, 256, dsm>>>(W, bias, out);
}

// round 10
// speedup vs baseline: 1.2560x; 1.0044x over previous
#include <cuda_runtime.h>

#define B_ 2
#define V_ 20000
#define C_ 32
#define NB_ 12
#define KS_ 9
#define OUT_ 32
#define NNODES (B_*V_)
#define KDIM 288          /* KS_*C_ */
#define MR2 40448         /* rows padded: 316 gemm blocks * 128 */

typedef unsigned long long u64;

// Scratch (module-allocated, zero-initialized; pad rows never written)
__device__ float g_ep[NNODES * 12];            // exp(ux+c), 12-padded (pads=0)
__device__ float g_em[NNODES * 16];            // exp(-ux), 16-padded 64B rows
__device__ float g_yt[(size_t)KDIM * MR2];     // TRANSPOSED y: [i][row], 46.6 MB

#define FMA_F32X2(d, a, b) \
    asm("fma.rn.f32x2 %0, %1, %2, %0;" : "+l"(d) : "l"(a), "l"(b))

__device__ __forceinline__ u64 pack2(float a, float b) {
    u64 r; asm("mov.b64 %0, {%1,%2};" : "=l"(r) : "f"(a), "f"(b)); return r;
}
__device__ __forceinline__ float lo32(u64 v) {
    float a, b; asm("mov.b64 {%0,%1}, %2;" : "=f"(a), "=f"(b) : "l"(v)); return a;
}
__device__ __forceinline__ float hi32(u64 v) {
    float a, b; asm("mov.b64 {%0,%1}, %2;" : "=f"(a), "=f"(b) : "l"(v)); return b;
}

// ---------------------------------------------------------------------------
// Kernel 1: ux = x.u ; E+[k]=exp(ux+c) (12-pad), E-[k]=exp(-ux) (16-pad rows).
// ---------------------------------------------------------------------------
__global__ void __launch_bounds__(512) k_ux(const float* __restrict__ x,
                                            const float* __restrict__ u,
                                            const float* __restrict__ cvec) {
    __shared__ float u_sm[C_ * KS_];
    __shared__ float c_sm[KS_];
    for (int i = threadIdx.x; i < C_ * KS_; i += 512) u_sm[i] = u[i];
    if (threadIdx.x < KS_) c_sm[threadIdx.x] = cvec[threadIdx.x];
    __syncthreads();

    int t = blockIdx.x * 512 + threadIdx.x;
    int node = t >> 2;
    int qq = t & 3;
    bool valid = node < NNODES;
    int nc = valid ? node : (NNODES - 1);

    const float4* xr = reinterpret_cast<const float4*>(x + (size_t)nc * C_) + qq * 2;
    float4 v0 = xr[0];
    float4 v1 = xr[1];
    float xs[8] = {v0.x, v0.y, v0.z, v0.w, v1.x, v1.y, v1.z, v1.w};

    float acc[KS_];
#pragma unroll
    for (int k = 0; k < KS_; k++) acc[k] = 0.f;
    const int cbase = qq * 8;
#pragma unroll
    for (int j = 0; j < 8; j++)
#pragma unroll
        for (int k = 0; k < KS_; k++)
            acc[k] = fmaf(xs[j], u_sm[(cbase + j) * KS_ + k], acc[k]);
#pragma unroll
    for (int k = 0; k < KS_; k++) acc[k] += __shfl_xor_sync(0xffffffffu, acc[k], 1);
#pragma unroll
    for (int k = 0; k < KS_; k++) acc[k] += __shfl_xor_sync(0xffffffffu, acc[k], 2);

    if (valid) {
        float4 me;
        if (qq == 0)
            me = make_float4(__expf(-acc[0]), __expf(-acc[1]), __expf(-acc[2]),
                             __expf(-acc[3]));
        else if (qq == 1)
            me = make_float4(__expf(-acc[4]), __expf(-acc[5]), __expf(-acc[6]),
                             __expf(-acc[7]));
        else if (qq == 2)
            me = make_float4(__expf(-acc[8]), 0.f, 0.f, 0.f);
        else
            me = make_float4(0.f, 0.f, 0.f, 0.f);
        reinterpret_cast<float4*>(g_em + (size_t)node * 16)[qq] = me;

        if (qq < 3) {
            float4 pe;
            if (qq < 2) {
                int kb = qq * 4;
                pe = make_float4(__expf(acc[kb] + c_sm[kb]),
                                 __expf(acc[kb + 1] + c_sm[kb + 1]),
                                 __expf(acc[kb + 2] + c_sm[kb + 2]),
                                 __expf(acc[kb + 3] + c_sm[kb + 3]));
            } else {
                pe = make_float4(__expf(acc[8] + c_sm[8]), 0.f, 0.f, 0.f);
            }
            reinterpret_cast<float4*>(g_ep + (size_t)node * 12)[qq] = pe;
        }
    }
}

// ---------------------------------------------------------------------------
// Kernel 2: attention + aggregation, output TRANSPOSED to g_yt[i][node].
// em staged cooperatively; q OVERWRITES the em staging rows in place
// (lane n: read em row -> compute q -> store q into same row; syncwarp-fenced).
// ---------------------------------------------------------------------------
#define EMS 20   /* smem stride (floats) for em/q rows */
__global__ void __launch_bounds__(256) k_attn(const float* __restrict__ x,
                                              const int* __restrict__ adj) {
    __shared__ float yb[KDIM * 32];            // 36 KB staging
    __shared__ float eq_sm[8][NB_ * EMS];      // 7.5 KB: em rows, then q rows

    const int tid = threadIdx.x;
    const int warp = tid >> 5;
    const int lane = tid & 31;
    const int node0 = blockIdx.x * 32;         // grid = 1250 exact

    int av[4];
#pragma unroll
    for (int it = 0; it < 4; it++) {
        int node = node0 + warp * 4 + it;
        int v = node % V_;
        av[it] = (lane < NB_) ? adj[v * NB_ + lane] : 0;
    }

    const int n1 = lane >> 2, j1 = lane & 3;   // cooperative gather mapping

#pragma unroll
    for (int it = 0; it < 4; it++) {
        const int l = warp * 4 + it;
        const int node = node0 + l;
        const int b = node / V_;
        const int a = av[it];

        unsigned nz = __ballot_sync(0xffffffffu, a != 0);
        int deg = __popc(nz);
        float inv_deg = deg ? (1.f / (float)deg) : 0.f;

        // cooperative em gather: neighbors 0..7 (all lanes), 8..11 (lanes 0..15)
        int an1 = __shfl_sync(0xffffffffu, a, n1);
        int an2 = __shfl_sync(0xffffffffu, a, (8 + n1) & 31);
        {
            int s1 = an1 ? (an1 - 1) : 0;
            float4 v1 = *reinterpret_cast<const float4*>(
                g_em + (size_t)(b * V_ + s1) * 16 + 4 * j1);
            *reinterpret_cast<float4*>(&eq_sm[warp][n1 * EMS + 4 * j1]) = v1;
            if (lane < 16) {
                int s2 = an2 ? (an2 - 1) : 0;
                float4 v2 = *reinterpret_cast<const float4*>(
                    g_em + (size_t)(b * V_ + s2) * 16 + 4 * j1);
                *reinterpret_cast<float4*>(&eq_sm[warp][(8 + n1) * EMS + 4 * j1]) = v2;
            }
        }
        __syncwarp();

        // lane n: read its em row, compute q, overwrite the row with q
        if (lane < NB_) {
            float4* qr = reinterpret_cast<float4*>(&eq_sm[warp][lane * EMS]);
            if (a) {
                float4 m0 = qr[0], m1 = qr[1], m2 = qr[2];
                const float4* ep4 = reinterpret_cast<const float4*>(
                    g_ep + (size_t)node * 12);
                float4 p0 = ep4[0], p1 = ep4[1], p2 = ep4[2];
                float q0 = p0.x * m0.x, q1 = p0.y * m0.y, q2 = p0.z * m0.z,
                      q3 = p0.w * m0.w;
                float q4 = p1.x * m1.x, q5 = p1.y * m1.y, q6 = p1.z * m1.z,
                      q7 = p1.w * m1.w;
                float q8 = p2.x * m2.x;
                float s = q0 + q1 + q2 + q3 + q4 + q5 + q6 + q7 + q8;
                float sc = inv_deg / s;
                qr[0] = make_float4(q0 * sc, q1 * sc, q2 * sc, q3 * sc);
                qr[1] = make_float4(q4 * sc, q5 * sc, q6 * sc, q7 * sc);
                qr[2] = make_float4(q8 * sc, 0.f, 0.f, 0.f);
            } else {
                qr[0] = make_float4(0.f, 0.f, 0.f, 0.f);
                qr[1] = make_float4(0.f, 0.f, 0.f, 0.f);
                qr[2] = make_float4(0.f, 0.f, 0.f, 0.f);
            }
        }
        __syncwarp();

        // batched neighbor x gathers (coalesced 128B rows, MLP=12)
        float xv[NB_];
#pragma unroll
        for (int n = 0; n < NB_; n++) {
            int an = __shfl_sync(0xffffffffu, a, n);
            int idx = an ? (an - 1) : 0;
            xv[n] = x[((size_t)b * V_ + idx) * C_ + lane];
        }

        u64 acc[5];
#pragma unroll
        for (int t = 0; t < 5; t++) acc[t] = 0ull;
#pragma unroll
        for (int n = 0; n < NB_; n++) {
            u64 xx = pack2(xv[n], xv[n]);
            const float4* q4 = reinterpret_cast<const float4*>(&eq_sm[warp][n * EMS]);
            float4 qa = q4[0], qb = q4[1], qc = q4[2];   // 3 broadcast LDS.128
            FMA_F32X2(acc[0], pack2(qa.x, qa.y), xx);
            FMA_F32X2(acc[1], pack2(qa.z, qa.w), xx);
            FMA_F32X2(acc[2], pack2(qb.x, qb.y), xx);
            FMA_F32X2(acc[3], pack2(qb.z, qb.w), xx);
            FMA_F32X2(acc[4], pack2(qc.x, qc.x), xx);
        }
        __syncwarp();   // q rows fully consumed before next iteration's em gather

        // swizzled smem store: yb[(k*32+lane)*32 + (l ^ lane)] (conflict-free)
        float vals[KS_] = {lo32(acc[0]), hi32(acc[0]), lo32(acc[1]), hi32(acc[1]),
                           lo32(acc[2]), hi32(acc[2]), lo32(acc[3]), hi32(acc[3]),
                           lo32(acc[4])};
#pragma unroll
        for (int k = 0; k < KS_; k++)
            yb[(k * 32 + lane) * 32 + (l ^ lane)] = vals[k];
    }
    __syncthreads();

    // coalesced transposed write-out: g_yt[i][node0 + l]
#pragma unroll
    for (int idx = tid; idx < KDIM * 32; idx += 256) {
        int i = idx >> 5, l = idx & 31;
        g_yt[(size_t)i * MR2 + node0 + l] = yb[(i << 5) + (l ^ (i & 31))];
    }
}

// ---------------------------------------------------------------------------
// Kernel 3: out = relu(Yt^T @ W2 + b). 256 thr, 128-row tile (316 blocks),
// 4 rows x 4 outs per thread: per i = 1 LDS.128(y) + 1 broadcast LDS.128(W)
// per 8 FFMA2. y double-buffered coalesced chunks.
// ---------------------------------------------------------------------------
#define GMT 128
#define GCH 16
#define NCHK (KDIM / GCH)   /* 18 */
__global__ void __launch_bounds__(256) k_gemm(const float* __restrict__ W,
                                              const float* __restrict__ bias,
                                              float* __restrict__ out) {
    extern __shared__ __align__(16) char dsm_raw[];
    u64* ws = reinterpret_cast<u64*>(dsm_raw);                      // 36 KB
    float* ych = reinterpret_cast<float*>(dsm_raw + KDIM * 16 * 8); // 2x16x128, 16 KB
    __shared__ float b_sm[OUT_];

    const int tid = threadIdx.x;

    // ws[i*16+op] = (W2[i][2op], W2[i][2op+1]);  W2[k*32+c][o] = W[c][k][o]
    for (int idx = tid; idx < KDIM * 16; idx += 256) {
        int i = idx >> 4, op = idx & 15;
        int c = i & 31, k = i >> 5;
        const float* w = W + c * KDIM + k * OUT_ + 2 * op;
        ws[idx] = pack2(w[0], w[1]);
    }
    if (tid < OUT_) b_sm[tid] = bias[tid];

    const int row0 = blockIdx.x * GMT;
    const int warp = tid >> 5, lane = tid & 31;
    const int og = warp;                // outs 4*og..4*og+3 (warp-uniform)
    const int stg_i = tid >> 7;         // staging: 2 i-rows per pass
    const int stg_c = tid & 127;

    u64 acc[4][2];
#pragma unroll
    for (int r = 0; r < 4; r++) { acc[r][0] = 0ull; acc[r][1] = 0ull; }

    // load chunk 0
#pragma unroll
    for (int e = 0; e < GCH / 2; e++) {
        int il = 2 * e + stg_i;
        ych[il * GMT + stg_c] = g_yt[(size_t)il * MR2 + row0 + stg_c];
    }
    __syncthreads();

#pragma unroll 1
    for (int ch = 0; ch < NCHK; ch++) {
        const int buf = ch & 1;

        float pre[GCH / 2];
        if (ch + 1 < NCHK) {
#pragma unroll
            for (int e = 0; e < GCH / 2; e++) {
                int il = 2 * e + stg_i;
                pre[e] = g_yt[(size_t)((ch + 1) * GCH + il) * MR2 + row0 + stg_c];
            }
        }

        const float* yc = &ych[buf * (GCH * GMT)];
#pragma unroll
        for (int il = 0; il < GCH; il++) {
            const int i = ch * GCH + il;
            float4 yv = *reinterpret_cast<const float4*>(&yc[il * GMT + 4 * lane]);
            u64 wv0, wv1;
            {
                ulonglong2 wl = *reinterpret_cast<const ulonglong2*>(
                    &ws[i * 16 + og * 2]);              // broadcast LDS.128
                wv0 = wl.x; wv1 = wl.y;
            }
            u64 yy0 = pack2(yv.x, yv.x);
            u64 yy1 = pack2(yv.y, yv.y);
            u64 yy2 = pack2(yv.z, yv.z);
            u64 yy3 = pack2(yv.w, yv.w);
            FMA_F32X2(acc[0][0], yy0, wv0); FMA_F32X2(acc[0][1], yy0, wv1);
            FMA_F32X2(acc[1][0], yy1, wv0); FMA_F32X2(acc[1][1], yy1, wv1);
            FMA_F32X2(acc[2][0], yy2, wv0); FMA_F32X2(acc[2][1], yy2, wv1);
            FMA_F32X2(acc[3][0], yy3, wv0); FMA_F32X2(acc[3][1], yy3, wv1);
        }

        if (ch + 1 < NCHK) {
#pragma unroll
            for (int e = 0; e < GCH / 2; e++) {
                int il = 2 * e + stg_i;
                ych[(buf ^ 1) * (GCH * GMT) + il * GMT + stg_c] = pre[e];
            }
        }
        __syncthreads();
    }

    // epilogue: rows row0 + 4*lane + r, outs 4*og..4*og+3
    const int ob = og * 4;
#pragma unroll
    for (int r = 0; r < 4; r++) {
        int grow = row0 + 4 * lane + r;
        if (grow < NNODES) {
            float4 ov;
            ov.x = fmaxf(lo32(acc[r][0]) + b_sm[ob + 0], 0.f);
            ov.y = fmaxf(hi32(acc[r][0]) + b_sm[ob + 1], 0.f);
            ov.z = fmaxf(lo32(acc[r][1]) + b_sm[ob + 2], 0.f);
            ov.w = fmaxf(hi32(acc[r][1]) + b_sm[ob + 3], 0.f);
            *reinterpret_cast<float4*>(out + (size_t)grow * OUT_ + ob) = ov;
        }
    }
}

// ---------------------------------------------------------------------------
// Inputs (metadata order): x, W, u, c, b, adj
// ---------------------------------------------------------------------------
extern "C" void kernel_launch(void* const* d_in, const int* in_sizes, int n_in,
                              void* d_out, int out_size) {
    const float* x    = (const float*)d_in[0];
    const float* W    = (const float*)d_in[1];
    const float* u    = (const float*)d_in[2];
    const float* cvec = (const float*)d_in[3];
    const float* bias = (const float*)d_in[4];
    const int*   adj  = (const int*)d_in[5];
    float* out = (float*)d_out;

    const int dsm = KDIM * 16 * 8 + 2 * GCH * GMT * 4;   // 36864 + 16384 = 53248
    cudaFuncSetAttribute(k_gemm, cudaFuncAttributeMaxDynamicSharedMemorySize, dsm);

    k_ux<<<(NNODES * 4 + 511) / 512, 512>>>(x, u, cvec);
    k_attn<<<NNODES / 32, 256>>>(x, adj);
    k_gemm<<<MR2 / GMT, 256, dsm>>>(W, bias, out);
}